// round 1
// baseline (speedup 1.0000x reference)
#include <cuda_runtime.h>

// Problem constants
#define Bn 2
#define Tn 2048
#define Dn 2048
#define Nh 16
#define Hd 128
#define Fr 64

// Scratch (device globals: allocation-free rule)
__device__ float g_q[(size_t)Bn * Nh * Tn * Hd];   // [b][n][t][h]
__device__ float g_k[(size_t)Bn * Nh * Tn * Hd];   // roped
__device__ float g_v[(size_t)Bn * Nh * Tn * Hd];   // roped
__device__ float g_o[(size_t)Bn * Tn * Dn];        // [b][t][n*H+h]

// ---------------------------------------------------------------------------
// SGEMM: C[M,NN] = A[M,K] @ B[K,NN], 128x128 block tile, 8x8 micro tile.
// MODE 0: A = x, B = w_attn (NN=6144). Epilogue splits q/k/v, applies RoPE to
//         k and v, writes head-major [b][n][t][h] into g_q/g_k/g_v.
// MODE 1: A = g_o, B = w_out (NN=2048). Plain write to C.
// All dims divisible by tile sizes -> no bounds checks.
// ---------------------------------------------------------------------------
template <int MODE>
__global__ __launch_bounds__(256)
void sgemm_k(const float* __restrict__ A, const float* __restrict__ Bm,
             float* __restrict__ C, const float* __restrict__ cosT,
             const float* __restrict__ sinT, int K, int NN)
{
    __shared__ float As[8][132];   // padded: conflict-free transposed stores
    __shared__ float Bs[8][128];

    const int tid = threadIdx.x;
    const int tx = tid & 15, ty = tid >> 4;
    const int bx = blockIdx.x, by = blockIdx.y;

    const float* Ap = (MODE == 0) ? A : g_o;

    float acc[8][8];
#pragma unroll
    for (int i = 0; i < 8; ++i)
#pragma unroll
        for (int j = 0; j < 8; ++j) acc[i][j] = 0.f;

    const int arow = tid >> 1;
    const int ac4  = (tid & 1) * 4;
    const int brow = tid >> 5;
    const int bc4  = (tid & 31) * 4;

    const float* Aload = Ap + (size_t)(by * 128 + arow) * K + ac4;
    const float* Bload = Bm + (size_t)brow * NN + bx * 128 + bc4;

    for (int kt = 0; kt < K; kt += 8) {
        float4 av = *(const float4*)(Aload + kt);
        float4 bv = *(const float4*)(Bload + (size_t)kt * NN);
        As[ac4 + 0][arow] = av.x;
        As[ac4 + 1][arow] = av.y;
        As[ac4 + 2][arow] = av.z;
        As[ac4 + 3][arow] = av.w;
        *(float4*)&Bs[brow][bc4] = bv;
        __syncthreads();
#pragma unroll
        for (int kk = 0; kk < 8; ++kk) {
            float af[8], bf[8];
            *(float4*)(af)     = *(const float4*)&As[kk][ty * 8];
            *(float4*)(af + 4) = *(const float4*)&As[kk][ty * 8 + 4];
            *(float4*)(bf)     = *(const float4*)&Bs[kk][tx * 8];
            *(float4*)(bf + 4) = *(const float4*)&Bs[kk][tx * 8 + 4];
#pragma unroll
            for (int i = 0; i < 8; ++i)
#pragma unroll
                for (int j = 0; j < 8; ++j)
                    acc[i][j] = fmaf(af[i], bf[j], acc[i][j]);
        }
        __syncthreads();
    }

    if (MODE == 0) {
        // Each block's 128-col span is exactly one head of one section.
        const int sec = bx >> 4;            // 0=q, 1=k, 2=v
        const int n   = bx & 15;            // head index
        float* dstBase = (sec == 0) ? g_q : (sec == 1) ? g_k : g_v;
        const int h0 = tx * 8;
#pragma unroll
        for (int i = 0; i < 8; ++i) {
            const int row = by * 128 + ty * 8 + i;
            const int b = row >> 11;        // row / T
            const int t = row & (Tn - 1);
            float vals[8];
            if (sec == 0) {
#pragma unroll
                for (int j = 0; j < 8; ++j) vals[j] = acc[i][j];
            } else {
                const float* cp = cosT + t * Fr;
                const float* sp = sinT + t * Fr;
#pragma unroll
                for (int j = 0; j < 8; j += 2) {
                    const int f = (h0 + j) >> 1;
                    const float cr = cp[f], si = sp[f];
                    const float xr = acc[i][j], xi = acc[i][j + 1];
                    vals[j]     = xr * cr - xi * si;
                    vals[j + 1] = xr * si + xi * cr;
                }
            }
            float* d = dstBase + (((size_t)(b * Nh + n) * Tn + t) * Hd + h0);
            *(float4*)d       = make_float4(vals[0], vals[1], vals[2], vals[3]);
            *(float4*)(d + 4) = make_float4(vals[4], vals[5], vals[6], vals[7]);
        }
    } else {
#pragma unroll
        for (int i = 0; i < 8; ++i) {
            const int row = by * 128 + ty * 8 + i;
            float* d = C + (size_t)row * NN + bx * 128 + tx * 8;
            *(float4*)d       = make_float4(acc[i][0], acc[i][1], acc[i][2], acc[i][3]);
            *(float4*)(d + 4) = make_float4(acc[i][4], acc[i][5], acc[i][6], acc[i][7]);
        }
    }
}

// ---------------------------------------------------------------------------
// Flash attention (causal), fp32. One block = (b, head, 64-row Q tile).
// S tile 64x64: thread (tx,ty) owns rows ty*4+r, cols tx+16*c (spread cols
//   -> conflict-free K smem reads at stride 129).
// O tile 64x128: same rows, cols tx*8+c (float4 V reads / O stores).
// ---------------------------------------------------------------------------
#define QS_STRIDE 132
#define KS_STRIDE 129
#define VS_STRIDE 132
#define PS_STRIDE 68
#define FLASH_SMEM ((64 * QS_STRIDE + 64 * KS_STRIDE + 64 * VS_STRIDE + 64 * PS_STRIDE) * 4)

__global__ __launch_bounds__(256)
void flash_k()
{
    extern __shared__ float sm[];
    float* Qs = sm;
    float* Ks = Qs + 64 * QS_STRIDE;
    float* Vs = Ks + 64 * KS_STRIDE;
    float* Ps = Vs + 64 * VS_STRIDE;

    const int qt = blockIdx.x, hn = blockIdx.y, b = blockIdx.z;
    const int tid = threadIdx.x;
    const int tx = tid & 15, ty = tid >> 4;
    const size_t bnoff = (size_t)(b * Nh + hn) * Tn * Hd;
    const float scale = 0.08838834764831843f;   // 1/sqrt(128), folded into Q

    const float* Qg = g_q + bnoff + (size_t)qt * 64 * Hd;
    for (int idx = tid; idx < 64 * 32; idx += 256) {
        const int r = idx >> 5, c4 = (idx & 31) * 4;
        float4 qv = *(const float4*)(Qg + r * Hd + c4);
        qv.x *= scale; qv.y *= scale; qv.z *= scale; qv.w *= scale;
        *(float4*)&Qs[r * QS_STRIDE + c4] = qv;
    }

    float m_i[4], l_i[4], accO[4][8];
#pragma unroll
    for (int r = 0; r < 4; ++r) {
        m_i[r] = -1e30f; l_i[r] = 0.f;
#pragma unroll
        for (int c = 0; c < 8; ++c) accO[r][c] = 0.f;
    }

    for (int kt = 0; kt <= qt; ++kt) {
        __syncthreads();   // prior PV reads done; Q stores visible on 1st iter
        const float* Kg = g_k + bnoff + (size_t)kt * 64 * Hd;
        const float* Vg = g_v + bnoff + (size_t)kt * 64 * Hd;
        for (int idx = tid; idx < 64 * 32; idx += 256) {
            const int r = idx >> 5, c4 = (idx & 31) * 4;
            float4 kv = *(const float4*)(Kg + r * Hd + c4);
            Ks[r * KS_STRIDE + c4 + 0] = kv.x;
            Ks[r * KS_STRIDE + c4 + 1] = kv.y;
            Ks[r * KS_STRIDE + c4 + 2] = kv.z;
            Ks[r * KS_STRIDE + c4 + 3] = kv.w;
            float4 vv = *(const float4*)(Vg + r * Hd + c4);
            *(float4*)&Vs[r * VS_STRIDE + c4] = vv;
        }
        __syncthreads();

        // S = Qs @ Ks^T   (rows ty*4+r, cols tx+16*c)
        float s[4][4];
#pragma unroll
        for (int r = 0; r < 4; ++r)
#pragma unroll
            for (int c = 0; c < 4; ++c) s[r][c] = 0.f;

#pragma unroll 4
        for (int h = 0; h < Hd; ++h) {
            float qf[4], kf[4];
#pragma unroll
            for (int r = 0; r < 4; ++r) qf[r] = Qs[(ty * 4 + r) * QS_STRIDE + h];
#pragma unroll
            for (int c = 0; c < 4; ++c) kf[c] = Ks[(tx + 16 * c) * KS_STRIDE + h];
#pragma unroll
            for (int r = 0; r < 4; ++r)
#pragma unroll
                for (int c = 0; c < 4; ++c)
                    s[r][c] = fmaf(qf[r], kf[c], s[r][c]);
        }

        if (kt == qt) {   // causal mask inside diagonal tile
#pragma unroll
            for (int r = 0; r < 4; ++r)
#pragma unroll
                for (int c = 0; c < 4; ++c)
                    if (tx + 16 * c > ty * 4 + r) s[r][c] = -1e30f;
        }

        // online softmax: row reductions across the 16 lanes sharing ty
        float mloc[4];
#pragma unroll
        for (int r = 0; r < 4; ++r) {
            mloc[r] = fmaxf(fmaxf(s[r][0], s[r][1]), fmaxf(s[r][2], s[r][3]));
        }
#pragma unroll
        for (int off = 8; off > 0; off >>= 1)
#pragma unroll
            for (int r = 0; r < 4; ++r)
                mloc[r] = fmaxf(mloc[r], __shfl_xor_sync(0xffffffffu, mloc[r], off));

        float alpha[4], p[4][4], ls[4];
#pragma unroll
        for (int r = 0; r < 4; ++r) {
            const float mn = fmaxf(m_i[r], mloc[r]);
            alpha[r] = __expf(m_i[r] - mn);
            m_i[r] = mn;
            float sum = 0.f;
#pragma unroll
            for (int c = 0; c < 4; ++c) {
                p[r][c] = __expf(s[r][c] - mn);
                sum += p[r][c];
            }
            ls[r] = sum;
        }
#pragma unroll
        for (int off = 8; off > 0; off >>= 1)
#pragma unroll
            for (int r = 0; r < 4; ++r)
                ls[r] += __shfl_xor_sync(0xffffffffu, ls[r], off);

#pragma unroll
        for (int r = 0; r < 4; ++r) {
            l_i[r] = l_i[r] * alpha[r] + ls[r];
#pragma unroll
            for (int c = 0; c < 8; ++c) accO[r][c] *= alpha[r];
#pragma unroll
            for (int c = 0; c < 4; ++c)
                Ps[(ty * 4 + r) * PS_STRIDE + tx + 16 * c] = p[r][c];
        }
        __syncthreads();

        // O += P @ V  (rows ty*4+r, cols tx*8+c)
#pragma unroll 4
        for (int j = 0; j < 64; ++j) {
            float pf[4];
#pragma unroll
            for (int r = 0; r < 4; ++r) pf[r] = Ps[(ty * 4 + r) * PS_STRIDE + j];
            float vf[8];
            *(float4*)(vf)     = *(const float4*)&Vs[j * VS_STRIDE + tx * 8];
            *(float4*)(vf + 4) = *(const float4*)&Vs[j * VS_STRIDE + tx * 8 + 4];
#pragma unroll
            for (int r = 0; r < 4; ++r)
#pragma unroll
                for (int c = 0; c < 8; ++c)
                    accO[r][c] = fmaf(pf[r], vf[c], accO[r][c]);
        }
    }

    // normalize + write to [b][t][n*H+h]
#pragma unroll
    for (int r = 0; r < 4; ++r) {
        const float inv = 1.0f / l_i[r];
        const int t = qt * 64 + ty * 4 + r;
        float* d = g_o + (size_t)(b * Tn + t) * Dn + hn * Hd + tx * 8;
        *(float4*)d       = make_float4(accO[r][0] * inv, accO[r][1] * inv,
                                        accO[r][2] * inv, accO[r][3] * inv);
        *(float4*)(d + 4) = make_float4(accO[r][4] * inv, accO[r][5] * inv,
                                        accO[r][6] * inv, accO[r][7] * inv);
    }
}

// ---------------------------------------------------------------------------
extern "C" void kernel_launch(void* const* d_in, const int* in_sizes, int n_in,
                              void* d_out, int out_size)
{
    const float* x      = (const float*)d_in[0];
    // d_in[1] = causal mask (structure known; unused)
    const float* cosT   = (const float*)d_in[2];
    const float* sinT   = (const float*)d_in[3];
    const float* w_attn = (const float*)d_in[4];
    const float* w_out  = (const float*)d_in[5];
    float* out          = (float*)d_out;

    cudaFuncSetAttribute(flash_k, cudaFuncAttributeMaxDynamicSharedMemorySize,
                         FLASH_SMEM);

    // 1) QKV GEMM + fused RoPE/head-transpose epilogue
    sgemm_k<0><<<dim3(48, 32), 256>>>(x, w_attn, nullptr, cosT, sinT, 2048, 6144);
    // 2) causal flash attention
    flash_k<<<dim3(Tn / 64, Nh, Bn), 256, FLASH_SMEM>>>();
    // 3) output projection
    sgemm_k<1><<<dim3(16, 32), 256>>>(nullptr, w_out, out, nullptr, nullptr,
                                      2048, 2048);
}

// round 2
// speedup vs baseline: 1.1662x; 1.1662x over previous
#include <cuda_runtime.h>
#include <cstdint>

// Problem constants
#define Bn 2
#define Tn 2048
#define Dn 2048
#define Nh 16
#define Hd 128
#define Fr 64

// Scratch (device globals: allocation-free rule)
__device__ float g_q[(size_t)Bn * Nh * Tn * Hd];   // [b][n][t][h]
__device__ float g_k[(size_t)Bn * Nh * Tn * Hd];   // roped
__device__ float g_v[(size_t)Bn * Nh * Tn * Hd];   // roped
__device__ float g_o[(size_t)Bn * Tn * Dn];        // [b][t][n*H+h]

// ---------------------------------------------------------------------------
// tf32 helpers: split fp32 into hi (tf32) + lo (tf32 of residual).
// acc += hi*hi + hi*lo + lo*hi  ==> ~2^-22 relative error (near-fp32).
// ---------------------------------------------------------------------------
__device__ __forceinline__ void split_tf32(float x, uint32_t& hi, uint32_t& lo)
{
    asm("cvt.rna.tf32.f32 %0, %1;" : "=r"(hi) : "f"(x));
    float r = x - __uint_as_float(hi);
    asm("cvt.rna.tf32.f32 %0, %1;" : "=r"(lo) : "f"(r));
}

__device__ __forceinline__ void mma_tf32(float* c, const uint32_t* a, const uint32_t* b)
{
    asm volatile(
        "mma.sync.aligned.m16n8k8.row.col.f32.tf32.tf32.f32 "
        "{%0,%1,%2,%3}, {%4,%5,%6,%7}, {%8,%9}, {%0,%1,%2,%3};\n"
        : "+f"(c[0]), "+f"(c[1]), "+f"(c[2]), "+f"(c[3])
        : "r"(a[0]), "r"(a[1]), "r"(a[2]), "r"(a[3]), "r"(b[0]), "r"(b[1]));
}

// ---------------------------------------------------------------------------
// Tensor-core GEMM (3xTF32): C[M,NN] = A[M,K] @ B[K,NN].
// Block tile 128x128, K-chunk 16. 8 warps (2m x 4n), warp tile 64x32,
// m16n8k8 fragments (4 m-tiles x 4 n-tiles per warp).
// MODE 0: A = x, B = w_attn (NN=6144); epilogue: split qkv, RoPE on k,v,
//         write head-major [b][n][t][h].
// MODE 1: A = g_o, B = w_out (NN=2048); plain store.
// ---------------------------------------------------------------------------
template <int MODE>
__global__ __launch_bounds__(256)
void tgemm_k(const float* __restrict__ A, const float* __restrict__ Bm,
             float* __restrict__ C, const float* __restrict__ cosT,
             const float* __restrict__ sinT, int K, int NN)
{
    __shared__ float As[16][132];   // [k][m], stride 132 (== 4 mod 32)
    __shared__ float Bs[16][132];   // [k][n]

    const int tid = threadIdx.x;
    const int wid = tid >> 5, lane = tid & 31;
    const int wm = wid >> 2, wn = wid & 3;        // warp grid 2 x 4
    const int grp = lane >> 2, tg = lane & 3;
    const int bx = blockIdx.x, by = blockIdx.y;

    const float* Ap = (MODE == 0) ? A : g_o;

    float acc[4][4][4];
#pragma unroll
    for (int mt = 0; mt < 4; ++mt)
#pragma unroll
        for (int nt = 0; nt < 4; ++nt)
#pragma unroll
            for (int r = 0; r < 4; ++r) acc[mt][nt][r] = 0.f;

    // global load addressing (A tile 128x16, B tile 16x128; float4 per thread x2)
    const int arow = tid >> 2;            // 0..63 (second half: +64)
    const int akq  = (tid & 3) * 4;
    const int bk   = tid >> 5;            // 0..7  (second half: +8)
    const int bn4  = (tid & 31) * 4;

    const float* Aptr = Ap + (size_t)(by * 128 + arow) * K + akq;
    const float* Bptr = Bm + (size_t)bk * NN + bx * 128 + bn4;

    float4 ar0 = *(const float4*)(Aptr);
    float4 ar1 = *(const float4*)(Aptr + (size_t)64 * K);
    float4 br0 = *(const float4*)(Bptr);
    float4 br1 = *(const float4*)(Bptr + (size_t)8 * NN);

    for (int kt = 0; kt < K; kt += 16) {
        __syncthreads();
        As[akq + 0][arow] = ar0.x;  As[akq + 1][arow] = ar0.y;
        As[akq + 2][arow] = ar0.z;  As[akq + 3][arow] = ar0.w;
        As[akq + 0][arow + 64] = ar1.x;  As[akq + 1][arow + 64] = ar1.y;
        As[akq + 2][arow + 64] = ar1.z;  As[akq + 3][arow + 64] = ar1.w;
        *(float4*)&Bs[bk][bn4]     = br0;
        *(float4*)&Bs[bk + 8][bn4] = br1;
        __syncthreads();

        if (kt + 16 < K) {   // prefetch next chunk; LDG overlaps MMA below
            ar0 = *(const float4*)(Aptr + kt + 16);
            ar1 = *(const float4*)(Aptr + (size_t)64 * K + kt + 16);
            br0 = *(const float4*)(Bptr + (size_t)(kt + 16) * NN);
            br1 = *(const float4*)(Bptr + (size_t)(kt + 24) * NN);
        }

#pragma unroll
        for (int ks = 0; ks < 2; ++ks) {
            const int kk = ks * 8;
            uint32_t ahi[4][4], alo[4][4], bhi[4][2], blo[4][2];
#pragma unroll
            for (int mt = 0; mt < 4; ++mt) {
                const int mb = wm * 64 + mt * 16 + grp;
                split_tf32(As[kk + tg][mb],         ahi[mt][0], alo[mt][0]);
                split_tf32(As[kk + tg][mb + 8],     ahi[mt][1], alo[mt][1]);
                split_tf32(As[kk + tg + 4][mb],     ahi[mt][2], alo[mt][2]);
                split_tf32(As[kk + tg + 4][mb + 8], ahi[mt][3], alo[mt][3]);
            }
#pragma unroll
            for (int nt = 0; nt < 4; ++nt) {
                const int nb = wn * 32 + nt * 8 + grp;
                split_tf32(Bs[kk + tg][nb],     bhi[nt][0], blo[nt][0]);
                split_tf32(Bs[kk + tg + 4][nb], bhi[nt][1], blo[nt][1]);
            }
#pragma unroll
            for (int mt = 0; mt < 4; ++mt)
#pragma unroll
                for (int nt = 0; nt < 4; ++nt) {
                    mma_tf32(acc[mt][nt], ahi[mt], bhi[nt]);
                    mma_tf32(acc[mt][nt], alo[mt], bhi[nt]);
                    mma_tf32(acc[mt][nt], ahi[mt], blo[nt]);
                }
        }
    }

    // Epilogue. Thread owns rows (grp + {0,8}) per m-tile, col pair 2*tg(+1)
    // per n-tile -> RoPE (even,odd) pairs land in one thread. float2 stores.
    if (MODE == 0) {
        const int sec = bx >> 4;            // 0=q 1=k 2=v
        const int nh  = bx & 15;
        float* dstBase = (sec == 0) ? g_q : (sec == 1) ? g_k : g_v;
#pragma unroll
        for (int mt = 0; mt < 4; ++mt) {
#pragma unroll
            for (int half = 0; half < 2; ++half) {
                const int row = by * 128 + wm * 64 + mt * 16 + grp + half * 8;
                const int b = row >> 11;
                const int t = row & (Tn - 1);
                const float* cp = cosT + t * Fr;
                const float* sp = sinT + t * Fr;
#pragma unroll
                for (int nt = 0; nt < 4; ++nt) {
                    const int h = wn * 32 + nt * 8 + tg * 2;
                    float v0 = acc[mt][nt][half * 2 + 0];
                    float v1 = acc[mt][nt][half * 2 + 1];
                    if (sec != 0) {
                        const float cr = cp[h >> 1], si = sp[h >> 1];
                        const float r0 = v0 * cr - v1 * si;
                        const float r1 = v0 * si + v1 * cr;
                        v0 = r0; v1 = r1;
                    }
                    float* d = dstBase + (((size_t)(b * Nh + nh) * Tn + t) * Hd + h);
                    *(float2*)d = make_float2(v0, v1);
                }
            }
        }
    } else {
#pragma unroll
        for (int mt = 0; mt < 4; ++mt)
#pragma unroll
            for (int half = 0; half < 2; ++half) {
                const int row = by * 128 + wm * 64 + mt * 16 + grp + half * 8;
#pragma unroll
                for (int nt = 0; nt < 4; ++nt) {
                    const int col = bx * 128 + wn * 32 + nt * 8 + tg * 2;
                    *(float2*)(C + (size_t)row * NN + col) =
                        make_float2(acc[mt][nt][half * 2 + 0],
                                    acc[mt][nt][half * 2 + 1]);
                }
            }
    }
}

// ---------------------------------------------------------------------------
// Flash attention (causal), fp32 (unchanged from R1).
// ---------------------------------------------------------------------------
#define QS_STRIDE 132
#define KS_STRIDE 129
#define VS_STRIDE 132
#define PS_STRIDE 68
#define FLASH_SMEM ((64 * QS_STRIDE + 64 * KS_STRIDE + 64 * VS_STRIDE + 64 * PS_STRIDE) * 4)

__global__ __launch_bounds__(256)
void flash_k()
{
    extern __shared__ float sm[];
    float* Qs = sm;
    float* Ks = Qs + 64 * QS_STRIDE;
    float* Vs = Ks + 64 * KS_STRIDE;
    float* Ps = Vs + 64 * VS_STRIDE;

    const int qt = blockIdx.x, hn = blockIdx.y, b = blockIdx.z;
    const int tid = threadIdx.x;
    const int tx = tid & 15, ty = tid >> 4;
    const size_t bnoff = (size_t)(b * Nh + hn) * Tn * Hd;
    const float scale = 0.08838834764831843f;

    const float* Qg = g_q + bnoff + (size_t)qt * 64 * Hd;
    for (int idx = tid; idx < 64 * 32; idx += 256) {
        const int r = idx >> 5, c4 = (idx & 31) * 4;
        float4 qv = *(const float4*)(Qg + r * Hd + c4);
        qv.x *= scale; qv.y *= scale; qv.z *= scale; qv.w *= scale;
        *(float4*)&Qs[r * QS_STRIDE + c4] = qv;
    }

    float m_i[4], l_i[4], accO[4][8];
#pragma unroll
    for (int r = 0; r < 4; ++r) {
        m_i[r] = -1e30f; l_i[r] = 0.f;
#pragma unroll
        for (int c = 0; c < 8; ++c) accO[r][c] = 0.f;
    }

    for (int kt = 0; kt <= qt; ++kt) {
        __syncthreads();
        const float* Kg = g_k + bnoff + (size_t)kt * 64 * Hd;
        const float* Vg = g_v + bnoff + (size_t)kt * 64 * Hd;
        for (int idx = tid; idx < 64 * 32; idx += 256) {
            const int r = idx >> 5, c4 = (idx & 31) * 4;
            float4 kv = *(const float4*)(Kg + r * Hd + c4);
            Ks[r * KS_STRIDE + c4 + 0] = kv.x;
            Ks[r * KS_STRIDE + c4 + 1] = kv.y;
            Ks[r * KS_STRIDE + c4 + 2] = kv.z;
            Ks[r * KS_STRIDE + c4 + 3] = kv.w;
            float4 vv = *(const float4*)(Vg + r * Hd + c4);
            *(float4*)&Vs[r * VS_STRIDE + c4] = vv;
        }
        __syncthreads();

        float s[4][4];
#pragma unroll
        for (int r = 0; r < 4; ++r)
#pragma unroll
            for (int c = 0; c < 4; ++c) s[r][c] = 0.f;

#pragma unroll 4
        for (int h = 0; h < Hd; ++h) {
            float qf[4], kf[4];
#pragma unroll
            for (int r = 0; r < 4; ++r) qf[r] = Qs[(ty * 4 + r) * QS_STRIDE + h];
#pragma unroll
            for (int c = 0; c < 4; ++c) kf[c] = Ks[(tx + 16 * c) * KS_STRIDE + h];
#pragma unroll
            for (int r = 0; r < 4; ++r)
#pragma unroll
                for (int c = 0; c < 4; ++c)
                    s[r][c] = fmaf(qf[r], kf[c], s[r][c]);
        }

        if (kt == qt) {
#pragma unroll
            for (int r = 0; r < 4; ++r)
#pragma unroll
                for (int c = 0; c < 4; ++c)
                    if (tx + 16 * c > ty * 4 + r) s[r][c] = -1e30f;
        }

        float mloc[4];
#pragma unroll
        for (int r = 0; r < 4; ++r)
            mloc[r] = fmaxf(fmaxf(s[r][0], s[r][1]), fmaxf(s[r][2], s[r][3]));
#pragma unroll
        for (int off = 8; off > 0; off >>= 1)
#pragma unroll
            for (int r = 0; r < 4; ++r)
                mloc[r] = fmaxf(mloc[r], __shfl_xor_sync(0xffffffffu, mloc[r], off));

        float alpha[4], p[4][4], ls[4];
#pragma unroll
        for (int r = 0; r < 4; ++r) {
            const float mn = fmaxf(m_i[r], mloc[r]);
            alpha[r] = __expf(m_i[r] - mn);
            m_i[r] = mn;
            float sum = 0.f;
#pragma unroll
            for (int c = 0; c < 4; ++c) {
                p[r][c] = __expf(s[r][c] - mn);
                sum += p[r][c];
            }
            ls[r] = sum;
        }
#pragma unroll
        for (int off = 8; off > 0; off >>= 1)
#pragma unroll
            for (int r = 0; r < 4; ++r)
                ls[r] += __shfl_xor_sync(0xffffffffu, ls[r], off);

#pragma unroll
        for (int r = 0; r < 4; ++r) {
            l_i[r] = l_i[r] * alpha[r] + ls[r];
#pragma unroll
            for (int c = 0; c < 8; ++c) accO[r][c] *= alpha[r];
#pragma unroll
            for (int c = 0; c < 4; ++c)
                Ps[(ty * 4 + r) * PS_STRIDE + tx + 16 * c] = p[r][c];
        }
        __syncthreads();

#pragma unroll 4
        for (int j = 0; j < 64; ++j) {
            float pf[4];
#pragma unroll
            for (int r = 0; r < 4; ++r) pf[r] = Ps[(ty * 4 + r) * PS_STRIDE + j];
            float vf[8];
            *(float4*)(vf)     = *(const float4*)&Vs[j * VS_STRIDE + tx * 8];
            *(float4*)(vf + 4) = *(const float4*)&Vs[j * VS_STRIDE + tx * 8 + 4];
#pragma unroll
            for (int r = 0; r < 4; ++r)
#pragma unroll
                for (int c = 0; c < 8; ++c)
                    accO[r][c] = fmaf(pf[r], vf[c], accO[r][c]);
        }
    }

#pragma unroll
    for (int r = 0; r < 4; ++r) {
        const float inv = 1.0f / l_i[r];
        const int t = qt * 64 + ty * 4 + r;
        float* d = g_o + (size_t)(b * Tn + t) * Dn + hn * Hd + tx * 8;
        *(float4*)d       = make_float4(accO[r][0] * inv, accO[r][1] * inv,
                                        accO[r][2] * inv, accO[r][3] * inv);
        *(float4*)(d + 4) = make_float4(accO[r][4] * inv, accO[r][5] * inv,
                                        accO[r][6] * inv, accO[r][7] * inv);
    }
}

// ---------------------------------------------------------------------------
extern "C" void kernel_launch(void* const* d_in, const int* in_sizes, int n_in,
                              void* d_out, int out_size)
{
    const float* x      = (const float*)d_in[0];
    // d_in[1] = causal mask (structure known; unused)
    const float* cosT   = (const float*)d_in[2];
    const float* sinT   = (const float*)d_in[3];
    const float* w_attn = (const float*)d_in[4];
    const float* w_out  = (const float*)d_in[5];
    float* out          = (float*)d_out;

    cudaFuncSetAttribute(flash_k, cudaFuncAttributeMaxDynamicSharedMemorySize,
                         FLASH_SMEM);

    // 1) QKV GEMM (3xTF32 tensor cores) + fused RoPE/head-transpose epilogue
    tgemm_k<0><<<dim3(48, 32), 256>>>(x, w_attn, nullptr, cosT, sinT, 2048, 6144);
    // 2) causal flash attention
    flash_k<<<dim3(Tn / 64, Nh, Bn), 256, FLASH_SMEM>>>();
    // 3) output projection (3xTF32 tensor cores)
    tgemm_k<1><<<dim3(16, 32), 256>>>(nullptr, w_out, out, nullptr, nullptr,
                                      2048, 2048);
}

// round 3
// speedup vs baseline: 1.2688x; 1.0880x over previous
#include <cuda_runtime.h>
#include <cstdint>

// Problem constants
#define Bn 2
#define Tn 2048
#define Dn 2048
#define Nh 16
#define Hd 128
#define Fr 64

// Scratch (device globals: allocation-free rule)
__device__ float g_q[(size_t)Bn * Nh * Tn * Hd];   // [b][n][t][h]
__device__ float g_k[(size_t)Bn * Nh * Tn * Hd];   // roped
__device__ float g_v[(size_t)Bn * Nh * Tn * Hd];   // roped
__device__ float g_o[(size_t)Bn * Tn * Dn];        // [b][t][n*H+h]

// ---------------------------------------------------------------------------
// tf32 helpers
// ---------------------------------------------------------------------------
__device__ __forceinline__ void split_tf32(float x, uint32_t& hi, uint32_t& lo)
{
    asm("cvt.rna.tf32.f32 %0, %1;" : "=r"(hi) : "f"(x));
    float r = x - __uint_as_float(hi);
    asm("cvt.rna.tf32.f32 %0, %1;" : "=r"(lo) : "f"(r));
}

__device__ __forceinline__ void mma_tf32(float* c, const uint32_t* a, const uint32_t* b)
{
    asm volatile(
        "mma.sync.aligned.m16n8k8.row.col.f32.tf32.tf32.f32 "
        "{%0,%1,%2,%3}, {%4,%5,%6,%7}, {%8,%9}, {%0,%1,%2,%3};\n"
        : "+f"(c[0]), "+f"(c[1]), "+f"(c[2]), "+f"(c[3])
        : "r"(a[0]), "r"(a[1]), "r"(a[2]), "r"(a[3]), "r"(b[0]), "r"(b[1]));
}

// ---------------------------------------------------------------------------
// Tensor-core GEMM (3xTF32, pre-split smem): C[M,NN] = A[M,K] @ B[K,NN].
// Block 128x128, K-chunk 16, 8 warps (2x4), warp tile 64x32.
// Split hi/lo computed ONCE at smem store; stride 136 => conflict-free LDS.
// ---------------------------------------------------------------------------
template <int MODE>
__global__ __launch_bounds__(256)
void tgemm_k(const float* __restrict__ A, const float* __restrict__ Bm,
             float* __restrict__ C, const float* __restrict__ cosT,
             const float* __restrict__ sinT, int K, int NN)
{
    __shared__ uint32_t Ahi[16][136], Alo[16][136];   // [k][m]
    __shared__ uint32_t Bhi[16][136], Blo[16][136];   // [k][n]

    const int tid = threadIdx.x;
    const int wid = tid >> 5, lane = tid & 31;
    const int wm = wid >> 2, wn = wid & 3;
    const int grp = lane >> 2, tg = lane & 3;
    const int bx = blockIdx.x, by = blockIdx.y;

    const float* Ap = (MODE == 0) ? A : g_o;

    float acc[4][4][4];
#pragma unroll
    for (int mt = 0; mt < 4; ++mt)
#pragma unroll
        for (int nt = 0; nt < 4; ++nt)
#pragma unroll
            for (int r = 0; r < 4; ++r) acc[mt][nt][r] = 0.f;

    const int arow = tid >> 2;            // 0..63 (+64 second half)
    const int akq  = (tid & 3) * 4;
    const int bk   = tid >> 5;            // 0..7 (+8 second half)
    const int bn4  = (tid & 31) * 4;

    const float* Aptr = Ap + (size_t)(by * 128 + arow) * K + akq;
    const float* Bptr = Bm + (size_t)bk * NN + bx * 128 + bn4;

    float4 ar0 = *(const float4*)(Aptr);
    float4 ar1 = *(const float4*)(Aptr + (size_t)64 * K);
    float4 br0 = *(const float4*)(Bptr);
    float4 br1 = *(const float4*)(Bptr + (size_t)8 * NN);

    for (int kt = 0; kt < K; kt += 16) {
        __syncthreads();
        // split-at-store: A transposed scatter (scalar), B packed uint4
        {
            uint32_t h, l;
            split_tf32(ar0.x, h, l); Ahi[akq + 0][arow] = h; Alo[akq + 0][arow] = l;
            split_tf32(ar0.y, h, l); Ahi[akq + 1][arow] = h; Alo[akq + 1][arow] = l;
            split_tf32(ar0.z, h, l); Ahi[akq + 2][arow] = h; Alo[akq + 2][arow] = l;
            split_tf32(ar0.w, h, l); Ahi[akq + 3][arow] = h; Alo[akq + 3][arow] = l;
            split_tf32(ar1.x, h, l); Ahi[akq + 0][arow + 64] = h; Alo[akq + 0][arow + 64] = l;
            split_tf32(ar1.y, h, l); Ahi[akq + 1][arow + 64] = h; Alo[akq + 1][arow + 64] = l;
            split_tf32(ar1.z, h, l); Ahi[akq + 2][arow + 64] = h; Alo[akq + 2][arow + 64] = l;
            split_tf32(ar1.w, h, l); Ahi[akq + 3][arow + 64] = h; Alo[akq + 3][arow + 64] = l;
            uint32_t h0, l0, h1, l1, h2, l2, h3, l3;
            split_tf32(br0.x, h0, l0); split_tf32(br0.y, h1, l1);
            split_tf32(br0.z, h2, l2); split_tf32(br0.w, h3, l3);
            *(uint4*)&Bhi[bk][bn4] = make_uint4(h0, h1, h2, h3);
            *(uint4*)&Blo[bk][bn4] = make_uint4(l0, l1, l2, l3);
            split_tf32(br1.x, h0, l0); split_tf32(br1.y, h1, l1);
            split_tf32(br1.z, h2, l2); split_tf32(br1.w, h3, l3);
            *(uint4*)&Bhi[bk + 8][bn4] = make_uint4(h0, h1, h2, h3);
            *(uint4*)&Blo[bk + 8][bn4] = make_uint4(l0, l1, l2, l3);
        }
        __syncthreads();

        if (kt + 16 < K) {
            ar0 = *(const float4*)(Aptr + kt + 16);
            ar1 = *(const float4*)(Aptr + (size_t)64 * K + kt + 16);
            br0 = *(const float4*)(Bptr + (size_t)(kt + 16) * NN);
            br1 = *(const float4*)(Bptr + (size_t)(kt + 24) * NN);
        }

#pragma unroll
        for (int ks = 0; ks < 2; ++ks) {
            const int kk = ks * 8;
            uint32_t ah[4][4], al[4][4], bh[4][2], bl[4][2];
#pragma unroll
            for (int mt = 0; mt < 4; ++mt) {
                const int mb = wm * 64 + mt * 16 + grp;
                ah[mt][0] = Ahi[kk + tg][mb];         al[mt][0] = Alo[kk + tg][mb];
                ah[mt][1] = Ahi[kk + tg][mb + 8];     al[mt][1] = Alo[kk + tg][mb + 8];
                ah[mt][2] = Ahi[kk + tg + 4][mb];     al[mt][2] = Alo[kk + tg + 4][mb];
                ah[mt][3] = Ahi[kk + tg + 4][mb + 8]; al[mt][3] = Alo[kk + tg + 4][mb + 8];
            }
#pragma unroll
            for (int nt = 0; nt < 4; ++nt) {
                const int nb = wn * 32 + nt * 8 + grp;
                bh[nt][0] = Bhi[kk + tg][nb];     bl[nt][0] = Blo[kk + tg][nb];
                bh[nt][1] = Bhi[kk + tg + 4][nb]; bl[nt][1] = Blo[kk + tg + 4][nb];
            }
#pragma unroll
            for (int mt = 0; mt < 4; ++mt)
#pragma unroll
                for (int nt = 0; nt < 4; ++nt) {
                    mma_tf32(acc[mt][nt], ah[mt], bh[nt]);
                    mma_tf32(acc[mt][nt], al[mt], bh[nt]);
                    mma_tf32(acc[mt][nt], ah[mt], bl[nt]);
                }
        }
    }

    if (MODE == 0) {
        const int sec = bx >> 4;
        const int nh  = bx & 15;
        float* dstBase = (sec == 0) ? g_q : (sec == 1) ? g_k : g_v;
#pragma unroll
        for (int mt = 0; mt < 4; ++mt) {
#pragma unroll
            for (int half = 0; half < 2; ++half) {
                const int row = by * 128 + wm * 64 + mt * 16 + grp + half * 8;
                const int b = row >> 11;
                const int t = row & (Tn - 1);
                const float* cp = cosT + t * Fr;
                const float* sp = sinT + t * Fr;
#pragma unroll
                for (int nt = 0; nt < 4; ++nt) {
                    const int h = wn * 32 + nt * 8 + tg * 2;
                    float v0 = acc[mt][nt][half * 2 + 0];
                    float v1 = acc[mt][nt][half * 2 + 1];
                    if (sec != 0) {
                        const float cr = cp[h >> 1], si = sp[h >> 1];
                        const float r0 = v0 * cr - v1 * si;
                        const float r1 = v0 * si + v1 * cr;
                        v0 = r0; v1 = r1;
                    }
                    float* d = dstBase + (((size_t)(b * Nh + nh) * Tn + t) * Hd + h);
                    *(float2*)d = make_float2(v0, v1);
                }
            }
        }
    } else {
#pragma unroll
        for (int mt = 0; mt < 4; ++mt)
#pragma unroll
            for (int half = 0; half < 2; ++half) {
                const int row = by * 128 + wm * 64 + mt * 16 + grp + half * 8;
#pragma unroll
                for (int nt = 0; nt < 4; ++nt) {
                    const int col = bx * 128 + wn * 32 + nt * 8 + tg * 2;
                    *(float2*)(C + (size_t)row * NN + col) =
                        make_float2(acc[mt][nt][half * 2 + 0],
                                    acc[mt][nt][half * 2 + 1]);
                }
            }
    }
}

// ---------------------------------------------------------------------------
// Tensor-core flash attention (causal), 3xTF32 for QK^T and P@V.
// Block: (qb, head, b); 8 warps; Q-tile 128 rows (16/warp), KV-tile 64.
// Fragments m16n8k8. fp32 tiles in smem; hi/lo split at fragment load.
// ---------------------------------------------------------------------------
#define FQT 128
#define FKT 64
#define QSS 132     // Q [m][h]    : frag banks 4*grp+tg  (conflict-free)
#define KSS 132     // K [kv][h]   : frag banks 4*grp+tg
#define VSS 136     // V [kv][h]   : frag banks 8*tg+grp
#define PSS 68      // P [m][kv]   : frag banks 4*grp+tg
#define FL_SMEM ((FQT * QSS + FKT * KSS + FKT * VSS + FQT * PSS) * 4)

__global__ __launch_bounds__(256)
void flash_tc()
{
    extern __shared__ float sm[];
    float* Qs = sm;
    float* Ks = Qs + FQT * QSS;
    float* Vs = Ks + FKT * KSS;
    float* Ps = Vs + FKT * VSS;

    const int qb = blockIdx.x, hn = blockIdx.y, b = blockIdx.z;
    const int tid = threadIdx.x;
    const int wid = tid >> 5, lane = tid & 31;
    const int grp = lane >> 2, tg = lane & 3;
    const size_t bnoff = (size_t)(b * Nh + hn) * Tn * Hd;
    const float scale = 0.08838834764831843f;   // 1/sqrt(128) folded into Q

    // load Q tile (scaled)
    const float* Qg = g_q + bnoff + (size_t)qb * FQT * Hd;
    for (int idx = tid; idx < FQT * 32; idx += 256) {
        const int r = idx >> 5, c4 = (idx & 31) * 4;
        float4 qv = *(const float4*)(Qg + r * Hd + c4);
        qv.x *= scale; qv.y *= scale; qv.z *= scale; qv.w *= scale;
        *(float4*)&Qs[r * QSS + c4] = qv;
    }

    float m_i[2] = {-1e30f, -1e30f}, l_i[2] = {0.f, 0.f};
    float accO[16][4];
#pragma unroll
    for (int nt = 0; nt < 16; ++nt)
#pragma unroll
        for (int r = 0; r < 4; ++r) accO[nt][r] = 0.f;

    const int qm = wid * 16 + grp;               // local q row (first of pair)
    const int mrow0 = qb * FQT + qm;             // absolute q row

    const int ktmax = 2 * qb + 1;
    for (int kt = 0; kt <= ktmax; ++kt) {
        __syncthreads();   // K/V (and P/V of prev iter) consumed; Qs ready (kt=0)
        const float* Kg = g_k + bnoff + (size_t)kt * FKT * Hd;
        const float* Vg = g_v + bnoff + (size_t)kt * FKT * Hd;
        for (int idx = tid; idx < FKT * 32; idx += 256) {
            const int r = idx >> 5, c4 = (idx & 31) * 4;
            *(float4*)&Ks[r * KSS + c4] = *(const float4*)(Kg + r * Hd + c4);
            *(float4*)&Vs[r * VSS + c4] = *(const float4*)(Vg + r * Hd + c4);
        }
        __syncthreads();

        // ---- S = Q @ K^T  (S tile 16x64 per warp: 8 n-tiles) ----
        float s[8][4];
#pragma unroll
        for (int nt = 0; nt < 8; ++nt)
#pragma unroll
            for (int r = 0; r < 4; ++r) s[nt][r] = 0.f;

#pragma unroll
        for (int ks = 0; ks < 16; ++ks) {
            uint32_t ah[4], al[4];
            split_tf32(Qs[qm * QSS + ks * 8 + tg],           ah[0], al[0]);
            split_tf32(Qs[(qm + 8) * QSS + ks * 8 + tg],     ah[1], al[1]);
            split_tf32(Qs[qm * QSS + ks * 8 + tg + 4],       ah[2], al[2]);
            split_tf32(Qs[(qm + 8) * QSS + ks * 8 + tg + 4], ah[3], al[3]);
#pragma unroll
            for (int nt = 0; nt < 8; ++nt) {
                uint32_t bh[2], bl[2];
                split_tf32(Ks[(nt * 8 + grp) * KSS + ks * 8 + tg],     bh[0], bl[0]);
                split_tf32(Ks[(nt * 8 + grp) * KSS + ks * 8 + tg + 4], bh[1], bl[1]);
                mma_tf32(s[nt], ah, bh);
                mma_tf32(s[nt], al, bh);
                mma_tf32(s[nt], ah, bl);
            }
        }

        // ---- causal mask (only tiles touching the diagonal) ----
        if (kt * FKT + FKT - 1 > qb * FQT + wid * 16) {
#pragma unroll
            for (int nt = 0; nt < 8; ++nt)
#pragma unroll
                for (int r = 0; r < 4; ++r) {
                    const int ka = kt * FKT + nt * 8 + 2 * tg + (r & 1);
                    const int ma = mrow0 + ((r >> 1) << 3);
                    if (ka > ma) s[nt][r] = -1e30f;
                }
        }

        // ---- online softmax (rows grp, grp+8; reduce over tg lanes) ----
        float mloc[2] = {-1e30f, -1e30f};
#pragma unroll
        for (int nt = 0; nt < 8; ++nt) {
            mloc[0] = fmaxf(mloc[0], fmaxf(s[nt][0], s[nt][1]));
            mloc[1] = fmaxf(mloc[1], fmaxf(s[nt][2], s[nt][3]));
        }
#pragma unroll
        for (int off = 1; off <= 2; off <<= 1) {
            mloc[0] = fmaxf(mloc[0], __shfl_xor_sync(0xffffffffu, mloc[0], off));
            mloc[1] = fmaxf(mloc[1], __shfl_xor_sync(0xffffffffu, mloc[1], off));
        }
        const float mn0 = fmaxf(m_i[0], mloc[0]);
        const float mn1 = fmaxf(m_i[1], mloc[1]);
        const float a0 = __expf(m_i[0] - mn0);
        const float a1 = __expf(m_i[1] - mn1);
        m_i[0] = mn0; m_i[1] = mn1;

        float ls0 = 0.f, ls1 = 0.f;
        float p[8][4];
#pragma unroll
        for (int nt = 0; nt < 8; ++nt) {
            p[nt][0] = __expf(s[nt][0] - mn0);
            p[nt][1] = __expf(s[nt][1] - mn0);
            p[nt][2] = __expf(s[nt][2] - mn1);
            p[nt][3] = __expf(s[nt][3] - mn1);
            ls0 += p[nt][0] + p[nt][1];
            ls1 += p[nt][2] + p[nt][3];
        }
#pragma unroll
        for (int off = 1; off <= 2; off <<= 1) {
            ls0 += __shfl_xor_sync(0xffffffffu, ls0, off);
            ls1 += __shfl_xor_sync(0xffffffffu, ls1, off);
        }
        l_i[0] = l_i[0] * a0 + ls0;
        l_i[1] = l_i[1] * a1 + ls1;

#pragma unroll
        for (int nt = 0; nt < 16; ++nt) {
            accO[nt][0] *= a0; accO[nt][1] *= a0;
            accO[nt][2] *= a1; accO[nt][3] *= a1;
        }

        // stage P to smem (warp-private rows) for A-fragment reload
#pragma unroll
        for (int nt = 0; nt < 8; ++nt) {
            *(float2*)&Ps[qm * PSS + nt * 8 + 2 * tg]       = make_float2(p[nt][0], p[nt][1]);
            *(float2*)&Ps[(qm + 8) * PSS + nt * 8 + 2 * tg] = make_float2(p[nt][2], p[nt][3]);
        }
        __syncwarp();

        // ---- O += P @ V  (16 h n-tiles) ----
#pragma unroll
        for (int ks = 0; ks < 8; ++ks) {
            uint32_t ph[4], pl[4];
            split_tf32(Ps[qm * PSS + ks * 8 + tg],           ph[0], pl[0]);
            split_tf32(Ps[(qm + 8) * PSS + ks * 8 + tg],     ph[1], pl[1]);
            split_tf32(Ps[qm * PSS + ks * 8 + tg + 4],       ph[2], pl[2]);
            split_tf32(Ps[(qm + 8) * PSS + ks * 8 + tg + 4], ph[3], pl[3]);
#pragma unroll
            for (int nt = 0; nt < 16; ++nt) {
                uint32_t vh[2], vl[2];
                split_tf32(Vs[(ks * 8 + tg) * VSS + nt * 8 + grp],     vh[0], vl[0]);
                split_tf32(Vs[(ks * 8 + tg + 4) * VSS + nt * 8 + grp], vh[1], vl[1]);
                mma_tf32(accO[nt], ph, vh);
                mma_tf32(accO[nt], pl, vh);
                mma_tf32(accO[nt], ph, vl);
            }
        }
    }

    // ---- epilogue: normalize, write [b][t][n*H+h] ----
    const float inv0 = 1.0f / l_i[0];
    const float inv1 = 1.0f / l_i[1];
    const int t0 = qb * FQT + wid * 16 + grp;
    const int t1 = t0 + 8;
    float* d0 = g_o + (size_t)(b * Tn + t0) * Dn + hn * Hd;
    float* d1 = g_o + (size_t)(b * Tn + t1) * Dn + hn * Hd;
#pragma unroll
    for (int nt = 0; nt < 16; ++nt) {
        const int h = nt * 8 + 2 * tg;
        *(float2*)(d0 + h) = make_float2(accO[nt][0] * inv0, accO[nt][1] * inv0);
        *(float2*)(d1 + h) = make_float2(accO[nt][2] * inv1, accO[nt][3] * inv1);
    }
}

// ---------------------------------------------------------------------------
extern "C" void kernel_launch(void* const* d_in, const int* in_sizes, int n_in,
                              void* d_out, int out_size)
{
    const float* x      = (const float*)d_in[0];
    // d_in[1] = causal mask (structure known; unused)
    const float* cosT   = (const float*)d_in[2];
    const float* sinT   = (const float*)d_in[3];
    const float* w_attn = (const float*)d_in[4];
    const float* w_out  = (const float*)d_in[5];
    float* out          = (float*)d_out;

    cudaFuncSetAttribute(flash_tc, cudaFuncAttributeMaxDynamicSharedMemorySize,
                         FL_SMEM);

    // 1) QKV GEMM (3xTF32) + fused RoPE/head-transpose epilogue
    tgemm_k<0><<<dim3(48, 32), 256>>>(x, w_attn, nullptr, cosT, sinT, 2048, 6144);
    // 2) causal flash attention (tensor cores)
    flash_tc<<<dim3(Tn / FQT, Nh, Bn), 256, FL_SMEM>>>();
    // 3) output projection (3xTF32)
    tgemm_k<1><<<dim3(16, 32), 256>>>(nullptr, w_out, out, nullptr, nullptr,
                                      2048, 2048);
}